// round 14
// baseline (speedup 1.0000x reference)
#include <cuda_runtime.h>
#include <cuda_bf16.h>
#include <cstdint>
#include <cstddef>

// ConvSelfAttention via mma.sync HMMA bf16 (ptxas target is plain sm_103 -> no tcgen05).
// Flash-style: exp(S) never leaves registers in k_attn; cp.async double-buffering;
// q pre-scaled by log2(e) so softmax exp is a single ex2.approx.
//
//  k_prep : Wqkv (q block x log2e), Wout -> bf16
//  k_qkv  : qkvT[n][o] = xT @ Wqkv^T  (x transposed+converted in-kernel)
//  k_lsum : L[i] = sum_j 2^(q'_i.k_j); epilogue writes vp[d][i] = val[d][i]/L[i]
//  k_attn : yT[j][d] = sum_i 2^(k_j.q'_i) * vp[d][i]  (S->exp->A2 in registers)
//  k_out  : out[o][j] = gamma * (yT @ Wout^T)^T[o][j] + x[o][j]

#define NTOK 4096
#define NB 8
#define LDT 72  // smem row pitch in bf16 (144B, 16B-aligned, ldmatrix conflict-free)

typedef __nv_bfloat16 bf16;
typedef unsigned int u32;

__device__ bf16 g_Wq[192 * 256];                 // [o][c] K-major (q rows pre-scaled)
__device__ bf16 g_Wo[256 * 64];                  // [o][d] K-major
__device__ bf16 g_qkvT[(size_t)NB * NTOK * 192]; // [b][n][o]  (q|k|v)
__device__ bf16 g_vp[(size_t)NB * 64 * NTOK];    // val/L  [b][d][i]
__device__ bf16 g_yT[(size_t)NB * NTOK * 64];    // [b][j][d]

extern __shared__ char dsm[];

// ---------------- helpers ----------------
__device__ __forceinline__ u32 s2u(const void* p) {
    u32 a;
    asm("{ .reg .u64 t; cvta.to.shared.u64 t, %1; cvt.u32.u64 %0, t; }" : "=r"(a) : "l"(p));
    return a;
}
__device__ __forceinline__ u32 pk_bf2(float lo, float hi) {
    u32 r;
    asm("cvt.rn.bf16x2.f32 %0, %1, %2;" : "=r"(r) : "f"(hi), "f"(lo));
    return r;
}
__device__ __forceinline__ float ex2f(float x) {
    float r;
    asm("ex2.approx.f32 %0, %1;" : "=f"(r) : "f"(x));
    return r;
}
__device__ __forceinline__ void ldm4(u32* r, u32 addr) {
    asm volatile("ldmatrix.sync.aligned.m8n8.x4.shared.b16 {%0,%1,%2,%3}, [%4];"
                 : "=r"(r[0]), "=r"(r[1]), "=r"(r[2]), "=r"(r[3]) : "r"(addr));
}
__device__ __forceinline__ void mma16816(float* c, const u32* a, u32 b0, u32 b1) {
    asm volatile(
        "mma.sync.aligned.m16n8k16.row.col.f32.bf16.bf16.f32 "
        "{%0,%1,%2,%3}, {%4,%5,%6,%7}, {%8,%9}, {%0,%1,%2,%3};"
        : "+f"(c[0]), "+f"(c[1]), "+f"(c[2]), "+f"(c[3])
        : "r"(a[0]), "r"(a[1]), "r"(a[2]), "r"(a[3]), "r"(b0), "r"(b1));
}
__device__ __forceinline__ u32 a_off(int l) {
    return (u32)((((l & 15) * LDT) + (l >> 4) * 8) * 2);
}
__device__ __forceinline__ u32 b_off(int l) {
    return (u32)(((((l & 7) + ((l >> 4) << 3)) * LDT) + ((l >> 3) & 1) * 8) * 2);
}
__device__ __forceinline__ void cpa16(u32 dst, const void* src) {
    asm volatile("cp.async.ca.shared.global [%0], [%1], 16;" :: "r"(dst), "l"(src));
}
__device__ __forceinline__ void cp_commit() {
    asm volatile("cp.async.commit_group;" ::: "memory");
}
template <int N>
__device__ __forceinline__ void cp_wait() {
    asm volatile("cp.async.wait_group %0;" :: "n"(N) : "memory");
}

// gmem (K-major rows of 64 bf16) -> smem tile with LDT pitch (synchronous)
__device__ __forceinline__ void load_tile(bf16* sm, const bf16* src, int rows, int stride) {
    for (int idx = threadIdx.x; idx < rows * 8; idx += blockDim.x) {
        int r = idx >> 3, c = idx & 7;
        *(uint4*)(sm + r * LDT + c * 8) = *(const uint4*)(src + (size_t)r * stride + c * 8);
    }
}
// async version
__device__ __forceinline__ void load_tile_async(u32 smbase, const bf16* src, int rows,
                                                int stride) {
    for (int idx = threadIdx.x; idx < rows * 8; idx += blockDim.x) {
        int r = idx >> 3, c = idx & 7;
        cpa16(smbase + (u32)((r * LDT + c * 8) * 2), src + (size_t)r * stride + c * 8);
    }
}

// Warp GEMM over one K=64 smem chunk (A and B both from smem).
template <int MT, int NTP>
__device__ __forceinline__ void wmma64(u32 sA, u32 sB, float (&acc)[MT][2 * NTP][4]) {
    const int l = threadIdx.x & 31;
    const u32 aoff = a_off(l), boff = b_off(l);
#pragma unroll
    for (int ks = 0; ks < 4; ks++) {
        u32 a[MT][4], b[NTP][4];
#pragma unroll
        for (int mt = 0; mt < MT; mt++)
            ldm4(a[mt], sA + aoff + (u32)((mt * 16 * LDT + ks * 16) * 2));
#pragma unroll
        for (int np = 0; np < NTP; np++)
            ldm4(b[np], sB + boff + (u32)((np * 16 * LDT + ks * 16) * 2));
#pragma unroll
        for (int mt = 0; mt < MT; mt++)
#pragma unroll
            for (int np = 0; np < NTP; np++) {
                mma16816(acc[mt][2 * np], a[mt], b[np][0], b[np][1]);
                mma16816(acc[mt][2 * np + 1], a[mt], b[np][2], b[np][3]);
            }
    }
}

// ---------------- k_prep: weights -> bf16, q block scaled by log2(e) ------------
__global__ void k_prep(const float* __restrict__ Wqkv, const float* __restrict__ Wout) {
    int idx = blockIdx.x * 256 + threadIdx.x;
    if (idx < 192 * 256) {
        float w = Wqkv[idx];
        if (idx < 64 * 256) w *= 1.4426950408889634f;  // log2(e) folded into q
        g_Wq[idx] = __float2bfloat16(w);
    } else {
        int j = idx - 192 * 256;
        if (j < 256 * 64) g_Wo[j] = __float2bfloat16(Wout[j]);
    }
}

// ---------------- k_qkv: qkvT[n][o] = xT @ Wq^T (x transposed in-kernel) --------
__global__ void __launch_bounds__(256) k_qkv(const float* __restrict__ x) {
    bf16* At = (bf16*)dsm;            // 128n x 64c (pitch 72) = 18432 B
    bf16* Bt = (bf16*)(dsm + 18432);  // 192 x 64             = 27648 B
    int b = blockIdx.y, n0 = blockIdx.x * 128;
    int tid = threadIdx.x, wid = tid >> 5, l = tid & 31;
    int wm = wid & 3, wn = wid >> 2;
    float acc[2][12][4];
#pragma unroll
    for (int mt = 0; mt < 2; mt++)
#pragma unroll
        for (int nt = 0; nt < 12; nt++)
#pragma unroll
            for (int e = 0; e < 4; e++) acc[mt][nt][e] = 0.f;

    for (int kc = 0; kc < 4; kc++) {
        __syncthreads();
        // transpose-load x chunk: c in [kc*64, kc*64+64), n in [n0, n0+128)
#pragma unroll
        for (int it = 0; it < 8; it++) {
            int lin = it * 256 + tid;  // (c4, n): 16 groups of 4 c  x 128 n
            int c4 = lin >> 7, nl = lin & 127;
            const float* xp = x + ((size_t)(b * 256 + kc * 64 + c4 * 4)) * NTOK + n0 + nl;
            float v0 = xp[0];
            float v1 = xp[NTOK];
            float v2 = xp[2 * NTOK];
            float v3 = xp[3 * NTOK];
            *(u32*)(At + nl * LDT + c4 * 4) = pk_bf2(v0, v1);
            *(u32*)(At + nl * LDT + c4 * 4 + 2) = pk_bf2(v2, v3);
        }
        load_tile(Bt, g_Wq + kc * 64, 192, 256);
        __syncthreads();
        wmma64<2, 6>(s2u(At) + (u32)(wm * 32 * LDT * 2),
                     s2u(Bt) + (u32)(wn * 96 * LDT * 2), acc);
    }
#pragma unroll
    for (int mt = 0; mt < 2; mt++)
#pragma unroll
        for (int nt = 0; nt < 12; nt++) {
            int j = n0 + wm * 32 + mt * 16 + (l >> 2);
            int o = wn * 96 + nt * 8 + (l & 3) * 2;
            *(u32*)(g_qkvT + ((size_t)b * NTOK + j) * 192 + o) =
                pk_bf2(acc[mt][nt][0], acc[mt][nt][1]);
            *(u32*)(g_qkvT + ((size_t)b * NTOK + j + 8) * 192 + o) =
                pk_bf2(acc[mt][nt][2], acc[mt][nt][3]);
        }
}

// ---------------- k_lsum: L[i] = sum_j 2^(q'_i.k_j); epilogue writes vp ----------
__global__ void __launch_bounds__(256, 2) k_lsum() {
    u32 kb[2] = {s2u(dsm), s2u(dsm) + 18432};  // two 128x72 bf16 tiles
    int b = blockIdx.y, i0 = blockIdx.x * 128;
    int tid = threadIdx.x, wid = tid >> 5, l = tid & 31;
    int wm = wid & 3, wn = wid >> 2;  // wm: i-warp (4x32), wn: j-half (2x64)

    const bf16* qsrc = g_qkvT + ((size_t)b * NTOK + i0) * 192;
    const bf16* ksrc = g_qkvT + (size_t)b * NTOK * 192 + 64;

    // stage q i-tile into kb0, capture A fragments
    load_tile_async(kb[0], qsrc, 128, 192);
    cp_commit();
    cp_wait<0>();
    __syncthreads();
    u32 qA[2][4][4];
    {
        u32 base = kb[0] + (u32)(wm * 32 * LDT * 2) + a_off(l);
#pragma unroll
        for (int mt = 0; mt < 2; mt++)
#pragma unroll
            for (int ks = 0; ks < 4; ks++)
                ldm4(qA[mt][ks], base + (u32)((mt * 16 * LDT + ks * 16) * 2));
    }
    __syncthreads();  // all warps done reading q from kb0

    // prefetch k-tiles 0 and 1  (k_jt lives in kb[(jt+1)&1])
    load_tile_async(kb[1], ksrc, 128, 192);
    cp_commit();
    load_tile_async(kb[0], ksrc + (size_t)128 * 192, 128, 192);
    cp_commit();

    float rs[2][2] = {{0.f, 0.f}, {0.f, 0.f}};
    const u32 boff = b_off(l);

    for (int jt = 0; jt < 32; jt++) {
        if (jt < 31) cp_wait<1>();
        else cp_wait<0>();
        __syncthreads();
        u32 kcur = kb[(jt + 1) & 1];
#pragma unroll
        for (int js = 0; js < 2; js++) {
            float S[2][4][4];
#pragma unroll
            for (int mt = 0; mt < 2; mt++)
#pragma unroll
                for (int nt = 0; nt < 4; nt++)
#pragma unroll
                    for (int e = 0; e < 4; e++) S[mt][nt][e] = 0.f;
            u32 bbase = kcur + (u32)((wn * 64 + js * 32) * LDT * 2) + boff;
#pragma unroll
            for (int ks = 0; ks < 4; ks++) {
                u32 bf[2][4];
#pragma unroll
                for (int np = 0; np < 2; np++)
                    ldm4(bf[np], bbase + (u32)((np * 16 * LDT + ks * 16) * 2));
#pragma unroll
                for (int mt = 0; mt < 2; mt++)
#pragma unroll
                    for (int np = 0; np < 2; np++) {
                        mma16816(S[mt][2 * np], qA[mt][ks], bf[np][0], bf[np][1]);
                        mma16816(S[mt][2 * np + 1], qA[mt][ks], bf[np][2], bf[np][3]);
                    }
            }
#pragma unroll
            for (int mt = 0; mt < 2; mt++)
#pragma unroll
                for (int nt = 0; nt < 4; nt++) {
                    rs[mt][0] += ex2f(S[mt][nt][0]) + ex2f(S[mt][nt][1]);
                    rs[mt][1] += ex2f(S[mt][nt][2]) + ex2f(S[mt][nt][3]);
                }
        }
        __syncthreads();  // done reading kcur; safe to overwrite
        if (jt + 2 < 32) {
            load_tile_async(kcur, ksrc + (size_t)((jt + 2) * 128) * 192, 128, 192);
            cp_commit();
        }
    }

    // ---- epilogue: L complete within this CTA -> write vp[d][i] = val[d][i]/L[i]
    float* sval = (float*)dsm;              // 64 x 129 f32 = 33016 B
    float* lred = (float*)(dsm + 33024);    // 2 x 128 f32 = 1024 B
#pragma unroll
    for (int mt = 0; mt < 2; mt++)
#pragma unroll
        for (int h = 0; h < 2; h++) {
            float s = rs[mt][h];
            s += __shfl_xor_sync(0xffffffffu, s, 1);
            s += __shfl_xor_sync(0xffffffffu, s, 2);
            if ((l & 3) == 0)
                lred[wn * 128 + wm * 32 + mt * 16 + h * 8 + (l >> 2)] = s;
        }
    __syncthreads();
    // scale + transpose val (128 i x 64 d) via smem
#pragma unroll
    for (int it = 0; it < 4; it++) {
        int lin = it * 256 + tid;  // il (0..127) x c8 (0..7)
        int il = lin >> 3, c8 = lin & 7;
        uint4 v4 = *(const uint4*)(g_qkvT + ((size_t)b * NTOK + i0 + il) * 192 + 128 + c8 * 8);
        float linv = 1.0f / (lred[il] + lred[128 + il]);
        const bf16* vb = (const bf16*)&v4;
#pragma unroll
        for (int e = 0; e < 8; e++)
            sval[(c8 * 8 + e) * 129 + il] = __bfloat162float(vb[e]) * linv;
    }
    __syncthreads();
#pragma unroll
    for (int it = 0; it < 4; it++) {
        int lin = it * 256 + tid;  // d (0..63) x seg (0..15), 8 i per seg
        int d = lin >> 4, seg = lin & 15;
        const float* sp = sval + d * 129 + seg * 8;
        uint4 w;
        w.x = pk_bf2(sp[0], sp[1]);
        w.y = pk_bf2(sp[2], sp[3]);
        w.z = pk_bf2(sp[4], sp[5]);
        w.w = pk_bf2(sp[6], sp[7]);
        *(uint4*)(g_vp + ((size_t)(b * 64 + d)) * NTOK + i0 + seg * 8) = w;
    }
}

// ---------------- k_attn: yT[j][d] = sum_i 2^(k_j.q'_i) vp[d][i] ----------------
// 8 warps x disjoint 16j x 64d output tiles; each warp covers the full 64-i chunk.
__global__ void __launch_bounds__(256, 2) k_attn() {
    u32 st[2] = {s2u(dsm), s2u(dsm) + 18432};
    int b = blockIdx.y, j0 = blockIdx.x * 128;
    int tid = threadIdx.x, wid = tid >> 5, l = tid & 31;

    const bf16* ksrc = g_qkvT + ((size_t)b * NTOK + j0) * 192 + 64;
    const bf16* qsrc = g_qkvT + (size_t)b * NTOK * 192;
    const bf16* vsrc = g_vp + (size_t)b * 64 * NTOK;

    // stage kT j-tile into st0 (128 rows), capture A fragments (16 j-rows per warp)
    load_tile_async(st[0], ksrc, 128, 192);
    cp_commit();
    cp_wait<0>();
    __syncthreads();
    u32 kA[4][4];
    {
        u32 base = st[0] + (u32)(wid * 16 * LDT * 2) + a_off(l);
#pragma unroll
        for (int ks = 0; ks < 4; ks++) ldm4(kA[ks], base + (u32)((ks * 16) * 2));
    }
    __syncthreads();

    // prefetch stages for ic 0 and 1  (chunk ic lives in st[(ic+1)&1])
    load_tile_async(st[1], qsrc, 64, 192);
    load_tile_async(st[1] + 9216, vsrc, 64, NTOK);
    cp_commit();
    load_tile_async(st[0], qsrc + (size_t)64 * 192, 64, 192);
    load_tile_async(st[0] + 9216, vsrc + 64, 64, NTOK);
    cp_commit();

    float ya[8][4];
#pragma unroll
    for (int nt = 0; nt < 8; nt++)
#pragma unroll
        for (int e = 0; e < 4; e++) ya[nt][e] = 0.f;

    const u32 boff = b_off(l);

    for (int ic = 0; ic < 64; ic++) {
        if (ic < 63) cp_wait<1>();
        else cp_wait<0>();
        __syncthreads();
        u32 cur = st[(ic + 1) & 1];
        // MMA1: S[16j x 64i], K=64 over d
        float S[8][4];
#pragma unroll
        for (int nt = 0; nt < 8; nt++)
#pragma unroll
            for (int e = 0; e < 4; e++) S[nt][e] = 0.f;
        u32 qb = cur + boff;
#pragma unroll
        for (int ks = 0; ks < 4; ks++) {
            u32 bq[4][4];
#pragma unroll
            for (int np = 0; np < 4; np++)
                ldm4(bq[np], qb + (u32)((np * 16 * LDT + ks * 16) * 2));
#pragma unroll
            for (int np = 0; np < 4; np++) {
                mma16816(S[2 * np], kA[ks], bq[np][0], bq[np][1]);
                mma16816(S[2 * np + 1], kA[ks], bq[np][2], bq[np][3]);
            }
        }
        // MMA2: ya[16j x 64d] += E[j][i] * vp[d][i]; E built per 16-i sub-chunk
        u32 vb = cur + 9216 + boff;
#pragma unroll
        for (int kc = 0; kc < 4; kc++) {
            u32 A2[4];
            A2[0] = pk_bf2(ex2f(S[2 * kc][0]), ex2f(S[2 * kc][1]));
            A2[1] = pk_bf2(ex2f(S[2 * kc][2]), ex2f(S[2 * kc][3]));
            A2[2] = pk_bf2(ex2f(S[2 * kc + 1][0]), ex2f(S[2 * kc + 1][1]));
            A2[3] = pk_bf2(ex2f(S[2 * kc + 1][2]), ex2f(S[2 * kc + 1][3]));
#pragma unroll
            for (int np = 0; np < 4; np++) {
                u32 bv[4];
                ldm4(bv, vb + (u32)((np * 16 * LDT + kc * 16) * 2));
                mma16816(ya[2 * np], A2, bv[0], bv[1]);
                mma16816(ya[2 * np + 1], A2, bv[2], bv[3]);
            }
        }
        __syncthreads();  // done reading cur; safe to overwrite
        if (ic + 2 < 64) {
            load_tile_async(cur, qsrc + (size_t)((ic + 2) * 64) * 192, 64, 192);
            load_tile_async(cur + 9216, vsrc + (ic + 2) * 64, 64, NTOK);
            cp_commit();
        }
    }

    // epilogue: direct bf16 write, disjoint per warp
    int j = j0 + wid * 16 + (l >> 2);
#pragma unroll
    for (int nt = 0; nt < 8; nt++) {
        int d = nt * 8 + (l & 3) * 2;
        *(u32*)(g_yT + ((size_t)b * NTOK + j) * 64 + d) = pk_bf2(ya[nt][0], ya[nt][1]);
        *(u32*)(g_yT + ((size_t)b * NTOK + j + 8) * 64 + d) = pk_bf2(ya[nt][2], ya[nt][3]);
    }
}

// ---------------- k_out ----------------
__global__ void __launch_bounds__(128) k_out(const float* __restrict__ x,
                                             const float* __restrict__ gamma,
                                             float* __restrict__ out) {
    bf16* At = (bf16*)dsm;            // yT tile 128x64 = 18432 B
    bf16* Bt = (bf16*)(dsm + 18432);  // Wo tile  64x64 =  9216 B
    float* Ts = (float*)dsm;          // reused: 64 x 132 f32 = 33792 B
    int j0 = blockIdx.x * 128, o0 = blockIdx.y * 64, b = blockIdx.z;
    int tid = threadIdx.x, wid = tid >> 5, l = tid & 31;
    load_tile(At, g_yT + ((size_t)b * NTOK + j0) * 64, 128, 64);
    load_tile(Bt, g_Wo + o0 * 64, 64, 64);
    __syncthreads();
    float acc[2][8][4];
#pragma unroll
    for (int mt = 0; mt < 2; mt++)
#pragma unroll
        for (int nt = 0; nt < 8; nt++)
#pragma unroll
            for (int e = 0; e < 4; e++) acc[mt][nt][e] = 0.f;
    wmma64<2, 4>(s2u(At) + (u32)(wid * 32 * LDT * 2), s2u(Bt), acc);
    __syncthreads();
#pragma unroll
    for (int mt = 0; mt < 2; mt++)
#pragma unroll
        for (int nt = 0; nt < 8; nt++) {
            int jl = wid * 32 + mt * 16 + (l >> 2);
            int ol = nt * 8 + (l & 3) * 2;
            Ts[ol * 132 + jl] = acc[mt][nt][0];
            Ts[(ol + 1) * 132 + jl] = acc[mt][nt][1];
            Ts[ol * 132 + jl + 8] = acc[mt][nt][2];
            Ts[(ol + 1) * 132 + jl + 8] = acc[mt][nt][3];
        }
    __syncthreads();
    float gm = gamma[0];
    int row = tid >> 1, half = (tid & 1) * 64;
    size_t goff = ((size_t)(b * 256 + o0 + row)) * NTOK + j0 + half;
#pragma unroll
    for (int q = 0; q < 16; q++) {
        float4 s = *(float4*)&Ts[row * 132 + half + q * 4];
        float4 xv = *(const float4*)&x[goff + q * 4];
        float4 o;
        o.x = fmaf(gm, s.x, xv.x);
        o.y = fmaf(gm, s.y, xv.y);
        o.z = fmaf(gm, s.z, xv.z);
        o.w = fmaf(gm, s.w, xv.w);
        *(float4*)&out[goff + q * 4] = o;
    }
}

extern "C" void kernel_launch(void* const* d_in, const int* in_sizes, int n_in,
                              void* d_out, int out_size) {
    const float* v = (const float*)d_in[0];
    const float* Wqkv = (const float*)d_in[1];
    const float* Wout = (const float*)d_in[2];
    const float* gamma = (const float*)d_in[3];
    float* out = (float*)d_out;

    k_prep<<<256, 256>>>(Wqkv, Wout);
    k_qkv<<<dim3(32, NB), 256, 18432 + 27648>>>(v);
    k_lsum<<<dim3(32, NB), 256, 36864>>>();
    k_attn<<<dim3(32, NB), 256, 36864>>>();
    k_out<<<dim3(32, 4, NB), 128, 33792>>>(v, gamma, out);
}

// round 15
// speedup vs baseline: 1.5950x; 1.5950x over previous
#include <cuda_runtime.h>
#include <cuda_bf16.h>
#include <cstdint>
#include <cstddef>

// ConvSelfAttention via mma.sync HMMA bf16 (ptxas target is plain sm_103 -> no tcgen05).
// Flash-style: exp(S) never leaves registers in k_attn; cp.async double-buffering;
// q pre-scaled by log2(e) so softmax exp is a single MUFU.EX2 (FTZ variant!).
//
//  k_prep : Wqkv (q block x log2e), Wout -> bf16
//  k_qkv  : qkvT[n][o] = xT @ Wqkv^T  (x transposed+converted in-kernel)
//  k_lsum : L[i] = sum_j 2^(q'_i.k_j); epilogue writes vp[d][i] = val[d][i]/L[i]
//  k_attn : yT[j][d] = sum_i 2^(k_j.q'_i) * vp[d][i]  (S->exp->A2 in registers)
//  k_out  : out[o][j] = gamma * (yT @ Wout^T)^T[o][j] + x[o][j]

#define NTOK 4096
#define NB 8
#define LDT 72  // smem row pitch in bf16 (144B, 16B-aligned, ldmatrix conflict-free)

typedef __nv_bfloat16 bf16;
typedef unsigned int u32;

__device__ bf16 g_Wq[192 * 256];                 // [o][c] K-major (q rows pre-scaled)
__device__ bf16 g_Wo[256 * 64];                  // [o][d] K-major
__device__ bf16 g_qkvT[(size_t)NB * NTOK * 192]; // [b][n][o]  (q|k|v)
__device__ bf16 g_vp[(size_t)NB * 64 * NTOK];    // val/L  [b][d][i]
__device__ bf16 g_yT[(size_t)NB * NTOK * 64];    // [b][j][d]

extern __shared__ char dsm[];

// ---------------- helpers ----------------
__device__ __forceinline__ u32 s2u(const void* p) {
    u32 a;
    asm("{ .reg .u64 t; cvta.to.shared.u64 t, %1; cvt.u32.u64 %0, t; }" : "=r"(a) : "l"(p));
    return a;
}
__device__ __forceinline__ u32 pk_bf2(float lo, float hi) {
    u32 r;
    asm("cvt.rn.bf16x2.f32 %0, %1, %2;" : "=r"(r) : "f"(hi), "f"(lo));
    return r;
}
__device__ __forceinline__ float ex2f(float x) {
    float r;
    asm("ex2.approx.ftz.f32 %0, %1;" : "=f"(r) : "f"(x));  // FTZ: single MUFU, no fixup
    return r;
}
__device__ __forceinline__ void ldm4(u32* r, u32 addr) {
    asm volatile("ldmatrix.sync.aligned.m8n8.x4.shared.b16 {%0,%1,%2,%3}, [%4];"
                 : "=r"(r[0]), "=r"(r[1]), "=r"(r[2]), "=r"(r[3]) : "r"(addr));
}
__device__ __forceinline__ void mma16816(float* c, const u32* a, u32 b0, u32 b1) {
    asm volatile(
        "mma.sync.aligned.m16n8k16.row.col.f32.bf16.bf16.f32 "
        "{%0,%1,%2,%3}, {%4,%5,%6,%7}, {%8,%9}, {%0,%1,%2,%3};"
        : "+f"(c[0]), "+f"(c[1]), "+f"(c[2]), "+f"(c[3])
        : "r"(a[0]), "r"(a[1]), "r"(a[2]), "r"(a[3]), "r"(b0), "r"(b1));
}
__device__ __forceinline__ u32 a_off(int l) {
    return (u32)((((l & 15) * LDT) + (l >> 4) * 8) * 2);
}
__device__ __forceinline__ u32 b_off(int l) {
    return (u32)(((((l & 7) + ((l >> 4) << 3)) * LDT) + ((l >> 3) & 1) * 8) * 2);
}
__device__ __forceinline__ void cpa16(u32 dst, const void* src) {
    asm volatile("cp.async.ca.shared.global [%0], [%1], 16;" :: "r"(dst), "l"(src));
}
__device__ __forceinline__ void cp_commit() {
    asm volatile("cp.async.commit_group;" ::: "memory");
}
template <int N>
__device__ __forceinline__ void cp_wait() {
    asm volatile("cp.async.wait_group %0;" :: "n"(N) : "memory");
}

// gmem (K-major rows of 64 bf16) -> smem tile with LDT pitch (synchronous)
__device__ __forceinline__ void load_tile(bf16* sm, const bf16* src, int rows, int stride) {
    for (int idx = threadIdx.x; idx < rows * 8; idx += blockDim.x) {
        int r = idx >> 3, c = idx & 7;
        *(uint4*)(sm + r * LDT + c * 8) = *(const uint4*)(src + (size_t)r * stride + c * 8);
    }
}
// async version
__device__ __forceinline__ void load_tile_async(u32 smbase, const bf16* src, int rows,
                                                int stride) {
    for (int idx = threadIdx.x; idx < rows * 8; idx += blockDim.x) {
        int r = idx >> 3, c = idx & 7;
        cpa16(smbase + (u32)((r * LDT + c * 8) * 2), src + (size_t)r * stride + c * 8);
    }
}

// Warp GEMM over one K=64 smem chunk (A and B both from smem).
template <int MT, int NTP>
__device__ __forceinline__ void wmma64(u32 sA, u32 sB, float (&acc)[MT][2 * NTP][4]) {
    const int l = threadIdx.x & 31;
    const u32 aoff = a_off(l), boff = b_off(l);
#pragma unroll
    for (int ks = 0; ks < 4; ks++) {
        u32 a[MT][4], b[NTP][4];
#pragma unroll
        for (int mt = 0; mt < MT; mt++)
            ldm4(a[mt], sA + aoff + (u32)((mt * 16 * LDT + ks * 16) * 2));
#pragma unroll
        for (int np = 0; np < NTP; np++)
            ldm4(b[np], sB + boff + (u32)((np * 16 * LDT + ks * 16) * 2));
#pragma unroll
        for (int mt = 0; mt < MT; mt++)
#pragma unroll
            for (int np = 0; np < NTP; np++) {
                mma16816(acc[mt][2 * np], a[mt], b[np][0], b[np][1]);
                mma16816(acc[mt][2 * np + 1], a[mt], b[np][2], b[np][3]);
            }
    }
}

// ---------------- k_prep: weights -> bf16, q block scaled by log2(e) ------------
__global__ void k_prep(const float* __restrict__ Wqkv, const float* __restrict__ Wout) {
    int idx = blockIdx.x * 256 + threadIdx.x;
    if (idx < 192 * 256) {
        float w = Wqkv[idx];
        if (idx < 64 * 256) w *= 1.4426950408889634f;  // log2(e) folded into q
        g_Wq[idx] = __float2bfloat16(w);
    } else {
        int j = idx - 192 * 256;
        if (j < 256 * 64) g_Wo[j] = __float2bfloat16(Wout[j]);
    }
}

// ---------------- k_qkv: qkvT[n][o] = xT @ Wq^T (x transposed in-kernel) --------
__global__ void __launch_bounds__(256) k_qkv(const float* __restrict__ x) {
    bf16* At = (bf16*)dsm;            // 128n x 64c (pitch 72) = 18432 B
    bf16* Bt = (bf16*)(dsm + 18432);  // 192 x 64             = 27648 B
    int b = blockIdx.y, n0 = blockIdx.x * 128;
    int tid = threadIdx.x, wid = tid >> 5, l = tid & 31;
    int wm = wid & 3, wn = wid >> 2;
    float acc[2][12][4];
#pragma unroll
    for (int mt = 0; mt < 2; mt++)
#pragma unroll
        for (int nt = 0; nt < 12; nt++)
#pragma unroll
            for (int e = 0; e < 4; e++) acc[mt][nt][e] = 0.f;

    for (int kc = 0; kc < 4; kc++) {
        __syncthreads();
        // transpose-load x chunk: c in [kc*64, kc*64+64), n in [n0, n0+128)
#pragma unroll
        for (int it = 0; it < 8; it++) {
            int lin = it * 256 + tid;  // (c4, n): 16 groups of 4 c  x 128 n
            int c4 = lin >> 7, nl = lin & 127;
            const float* xp = x + ((size_t)(b * 256 + kc * 64 + c4 * 4)) * NTOK + n0 + nl;
            float v0 = xp[0];
            float v1 = xp[NTOK];
            float v2 = xp[2 * NTOK];
            float v3 = xp[3 * NTOK];
            *(u32*)(At + nl * LDT + c4 * 4) = pk_bf2(v0, v1);
            *(u32*)(At + nl * LDT + c4 * 4 + 2) = pk_bf2(v2, v3);
        }
        load_tile(Bt, g_Wq + kc * 64, 192, 256);
        __syncthreads();
        wmma64<2, 6>(s2u(At) + (u32)(wm * 32 * LDT * 2),
                     s2u(Bt) + (u32)(wn * 96 * LDT * 2), acc);
    }
#pragma unroll
    for (int mt = 0; mt < 2; mt++)
#pragma unroll
        for (int nt = 0; nt < 12; nt++) {
            int j = n0 + wm * 32 + mt * 16 + (l >> 2);
            int o = wn * 96 + nt * 8 + (l & 3) * 2;
            *(u32*)(g_qkvT + ((size_t)b * NTOK + j) * 192 + o) =
                pk_bf2(acc[mt][nt][0], acc[mt][nt][1]);
            *(u32*)(g_qkvT + ((size_t)b * NTOK + j + 8) * 192 + o) =
                pk_bf2(acc[mt][nt][2], acc[mt][nt][3]);
        }
}

// ---------------- k_lsum: L[i] = sum_j 2^(q'_i.k_j); epilogue writes vp ----------
__global__ void __launch_bounds__(256, 2) k_lsum() {
    u32 kb[2] = {s2u(dsm), s2u(dsm) + 18432};  // two 128x72 bf16 tiles
    int b = blockIdx.y, i0 = blockIdx.x * 128;
    int tid = threadIdx.x, wid = tid >> 5, l = tid & 31;
    int wm = wid & 3, wn = wid >> 2;  // wm: i-warp (4x32), wn: j-half (2x64)

    const bf16* qsrc = g_qkvT + ((size_t)b * NTOK + i0) * 192;
    const bf16* ksrc = g_qkvT + (size_t)b * NTOK * 192 + 64;

    // stage q i-tile into kb0, capture A fragments
    load_tile_async(kb[0], qsrc, 128, 192);
    cp_commit();
    cp_wait<0>();
    __syncthreads();
    u32 qA[2][4][4];
    {
        u32 base = kb[0] + (u32)(wm * 32 * LDT * 2) + a_off(l);
#pragma unroll
        for (int mt = 0; mt < 2; mt++)
#pragma unroll
            for (int ks = 0; ks < 4; ks++)
                ldm4(qA[mt][ks], base + (u32)((mt * 16 * LDT + ks * 16) * 2));
    }
    __syncthreads();  // all warps done reading q from kb0

    // prefetch k-tiles 0 and 1  (k_jt lives in kb[(jt+1)&1])
    load_tile_async(kb[1], ksrc, 128, 192);
    cp_commit();
    load_tile_async(kb[0], ksrc + (size_t)128 * 192, 128, 192);
    cp_commit();

    float rs[2][2] = {{0.f, 0.f}, {0.f, 0.f}};
    const u32 boff = b_off(l);

    for (int jt = 0; jt < 32; jt++) {
        if (jt < 31) cp_wait<1>();
        else cp_wait<0>();
        __syncthreads();
        u32 kcur = kb[(jt + 1) & 1];
#pragma unroll
        for (int js = 0; js < 2; js++) {
            float S[2][4][4];
#pragma unroll
            for (int mt = 0; mt < 2; mt++)
#pragma unroll
                for (int nt = 0; nt < 4; nt++)
#pragma unroll
                    for (int e = 0; e < 4; e++) S[mt][nt][e] = 0.f;
            u32 bbase = kcur + (u32)((wn * 64 + js * 32) * LDT * 2) + boff;
#pragma unroll
            for (int ks = 0; ks < 4; ks++) {
                u32 bf[2][4];
#pragma unroll
                for (int np = 0; np < 2; np++)
                    ldm4(bf[np], bbase + (u32)((np * 16 * LDT + ks * 16) * 2));
#pragma unroll
                for (int mt = 0; mt < 2; mt++)
#pragma unroll
                    for (int np = 0; np < 2; np++) {
                        mma16816(S[mt][2 * np], qA[mt][ks], bf[np][0], bf[np][1]);
                        mma16816(S[mt][2 * np + 1], qA[mt][ks], bf[np][2], bf[np][3]);
                    }
            }
#pragma unroll
            for (int mt = 0; mt < 2; mt++)
#pragma unroll
                for (int nt = 0; nt < 4; nt++) {
                    rs[mt][0] += ex2f(S[mt][nt][0]) + ex2f(S[mt][nt][1]);
                    rs[mt][1] += ex2f(S[mt][nt][2]) + ex2f(S[mt][nt][3]);
                }
        }
        __syncthreads();  // done reading kcur; safe to overwrite
        if (jt + 2 < 32) {
            load_tile_async(kcur, ksrc + (size_t)((jt + 2) * 128) * 192, 128, 192);
            cp_commit();
        }
    }

    // ---- epilogue: L complete within this CTA -> write vp[d][i] = val[d][i]/L[i]
    float* sval = (float*)dsm;              // 64 x 129 f32 = 33016 B
    float* lred = (float*)(dsm + 33024);    // 2 x 128 f32 = 1024 B
#pragma unroll
    for (int mt = 0; mt < 2; mt++)
#pragma unroll
        for (int h = 0; h < 2; h++) {
            float s = rs[mt][h];
            s += __shfl_xor_sync(0xffffffffu, s, 1);
            s += __shfl_xor_sync(0xffffffffu, s, 2);
            if ((l & 3) == 0)
                lred[wn * 128 + wm * 32 + mt * 16 + h * 8 + (l >> 2)] = s;
        }
    __syncthreads();
    // scale + transpose val (128 i x 64 d) via smem
#pragma unroll
    for (int it = 0; it < 4; it++) {
        int lin = it * 256 + tid;  // il (0..127) x c8 (0..7)
        int il = lin >> 3, c8 = lin & 7;
        uint4 v4 = *(const uint4*)(g_qkvT + ((size_t)b * NTOK + i0 + il) * 192 + 128 + c8 * 8);
        float linv = 1.0f / (lred[il] + lred[128 + il]);
        const bf16* vb = (const bf16*)&v4;
#pragma unroll
        for (int e = 0; e < 8; e++)
            sval[(c8 * 8 + e) * 129 + il] = __bfloat162float(vb[e]) * linv;
    }
    __syncthreads();
#pragma unroll
    for (int it = 0; it < 4; it++) {
        int lin = it * 256 + tid;  // d (0..63) x seg (0..15), 8 i per seg
        int d = lin >> 4, seg = lin & 15;
        const float* sp = sval + d * 129 + seg * 8;
        uint4 w;
        w.x = pk_bf2(sp[0], sp[1]);
        w.y = pk_bf2(sp[2], sp[3]);
        w.z = pk_bf2(sp[4], sp[5]);
        w.w = pk_bf2(sp[6], sp[7]);
        *(uint4*)(g_vp + ((size_t)(b * 64 + d)) * NTOK + i0 + seg * 8) = w;
    }
}

// ---------------- k_attn: yT[j][d] = sum_i 2^(k_j.q'_i) vp[d][i] ----------------
// 8 warps x disjoint 16j x 64d output tiles; each warp covers the full 64-i chunk.
__global__ void __launch_bounds__(256, 2) k_attn() {
    u32 st[2] = {s2u(dsm), s2u(dsm) + 18432};
    int b = blockIdx.y, j0 = blockIdx.x * 128;
    int tid = threadIdx.x, wid = tid >> 5, l = tid & 31;

    const bf16* ksrc = g_qkvT + ((size_t)b * NTOK + j0) * 192 + 64;
    const bf16* qsrc = g_qkvT + (size_t)b * NTOK * 192;
    const bf16* vsrc = g_vp + (size_t)b * 64 * NTOK;

    // stage kT j-tile into st0 (128 rows), capture A fragments (16 j-rows per warp)
    load_tile_async(st[0], ksrc, 128, 192);
    cp_commit();
    cp_wait<0>();
    __syncthreads();
    u32 kA[4][4];
    {
        u32 base = st[0] + (u32)(wid * 16 * LDT * 2) + a_off(l);
#pragma unroll
        for (int ks = 0; ks < 4; ks++) ldm4(kA[ks], base + (u32)((ks * 16) * 2));
    }
    __syncthreads();

    // prefetch stages for ic 0 and 1  (chunk ic lives in st[(ic+1)&1])
    load_tile_async(st[1], qsrc, 64, 192);
    load_tile_async(st[1] + 9216, vsrc, 64, NTOK);
    cp_commit();
    load_tile_async(st[0], qsrc + (size_t)64 * 192, 64, 192);
    load_tile_async(st[0] + 9216, vsrc + 64, 64, NTOK);
    cp_commit();

    float ya[8][4];
#pragma unroll
    for (int nt = 0; nt < 8; nt++)
#pragma unroll
        for (int e = 0; e < 4; e++) ya[nt][e] = 0.f;

    const u32 boff = b_off(l);

    for (int ic = 0; ic < 64; ic++) {
        if (ic < 63) cp_wait<1>();
        else cp_wait<0>();
        __syncthreads();
        u32 cur = st[(ic + 1) & 1];
        // MMA1: S[16j x 64i], K=64 over d
        float S[8][4];
#pragma unroll
        for (int nt = 0; nt < 8; nt++)
#pragma unroll
            for (int e = 0; e < 4; e++) S[nt][e] = 0.f;
        u32 qb = cur + boff;
#pragma unroll
        for (int ks = 0; ks < 4; ks++) {
            u32 bq[4][4];
#pragma unroll
            for (int np = 0; np < 4; np++)
                ldm4(bq[np], qb + (u32)((np * 16 * LDT + ks * 16) * 2));
#pragma unroll
            for (int np = 0; np < 4; np++) {
                mma16816(S[2 * np], kA[ks], bq[np][0], bq[np][1]);
                mma16816(S[2 * np + 1], kA[ks], bq[np][2], bq[np][3]);
            }
        }
        // MMA2: ya[16j x 64d] += E[j][i] * vp[d][i]; E built per 16-i sub-chunk
        u32 vb = cur + 9216 + boff;
#pragma unroll
        for (int kc = 0; kc < 4; kc++) {
            u32 A2[4];
            A2[0] = pk_bf2(ex2f(S[2 * kc][0]), ex2f(S[2 * kc][1]));
            A2[1] = pk_bf2(ex2f(S[2 * kc][2]), ex2f(S[2 * kc][3]));
            A2[2] = pk_bf2(ex2f(S[2 * kc + 1][0]), ex2f(S[2 * kc + 1][1]));
            A2[3] = pk_bf2(ex2f(S[2 * kc + 1][2]), ex2f(S[2 * kc + 1][3]));
#pragma unroll
            for (int np = 0; np < 4; np++) {
                u32 bv[4];
                ldm4(bv, vb + (u32)((np * 16 * LDT + kc * 16) * 2));
                mma16816(ya[2 * np], A2, bv[0], bv[1]);
                mma16816(ya[2 * np + 1], A2, bv[2], bv[3]);
            }
        }
        __syncthreads();  // done reading cur; safe to overwrite
        if (ic + 2 < 64) {
            load_tile_async(cur, qsrc + (size_t)((ic + 2) * 64) * 192, 64, 192);
            load_tile_async(cur + 9216, vsrc + (ic + 2) * 64, 64, NTOK);
            cp_commit();
        }
    }

    // epilogue: direct bf16 write, disjoint per warp
    int j = j0 + wid * 16 + (l >> 2);
#pragma unroll
    for (int nt = 0; nt < 8; nt++) {
        int d = nt * 8 + (l & 3) * 2;
        *(u32*)(g_yT + ((size_t)b * NTOK + j) * 64 + d) = pk_bf2(ya[nt][0], ya[nt][1]);
        *(u32*)(g_yT + ((size_t)b * NTOK + j + 8) * 64 + d) = pk_bf2(ya[nt][2], ya[nt][3]);
    }
}

// ---------------- k_out ----------------
__global__ void __launch_bounds__(128) k_out(const float* __restrict__ x,
                                             const float* __restrict__ gamma,
                                             float* __restrict__ out) {
    bf16* At = (bf16*)dsm;            // yT tile 128x64 = 18432 B
    bf16* Bt = (bf16*)(dsm + 18432);  // Wo tile  64x64 =  9216 B
    float* Ts = (float*)dsm;          // reused: 64 x 132 f32 = 33792 B
    int j0 = blockIdx.x * 128, o0 = blockIdx.y * 64, b = blockIdx.z;
    int tid = threadIdx.x, wid = tid >> 5, l = tid & 31;
    load_tile(At, g_yT + ((size_t)b * NTOK + j0) * 64, 128, 64);
    load_tile(Bt, g_Wo + o0 * 64, 64, 64);
    __syncthreads();
    float acc[2][8][4];
#pragma unroll
    for (int mt = 0; mt < 2; mt++)
#pragma unroll
        for (int nt = 0; nt < 8; nt++)
#pragma unroll
            for (int e = 0; e < 4; e++) acc[mt][nt][e] = 0.f;
    wmma64<2, 4>(s2u(At) + (u32)(wid * 32 * LDT * 2), s2u(Bt), acc);
    __syncthreads();
#pragma unroll
    for (int mt = 0; mt < 2; mt++)
#pragma unroll
        for (int nt = 0; nt < 8; nt++) {
            int jl = wid * 32 + mt * 16 + (l >> 2);
            int ol = nt * 8 + (l & 3) * 2;
            Ts[ol * 132 + jl] = acc[mt][nt][0];
            Ts[(ol + 1) * 132 + jl] = acc[mt][nt][1];
            Ts[ol * 132 + jl + 8] = acc[mt][nt][2];
            Ts[(ol + 1) * 132 + jl + 8] = acc[mt][nt][3];
        }
    __syncthreads();
    float gm = gamma[0];
    int row = tid >> 1, half = (tid & 1) * 64;
    size_t goff = ((size_t)(b * 256 + o0 + row)) * NTOK + j0 + half;
#pragma unroll
    for (int q = 0; q < 16; q++) {
        float4 s = *(float4*)&Ts[row * 132 + half + q * 4];
        float4 xv = *(const float4*)&x[goff + q * 4];
        float4 o;
        o.x = fmaf(gm, s.x, xv.x);
        o.y = fmaf(gm, s.y, xv.y);
        o.z = fmaf(gm, s.z, xv.z);
        o.w = fmaf(gm, s.w, xv.w);
        *(float4*)&out[goff + q * 4] = o;
    }
}

extern "C" void kernel_launch(void* const* d_in, const int* in_sizes, int n_in,
                              void* d_out, int out_size) {
    const float* v = (const float*)d_in[0];
    const float* Wqkv = (const float*)d_in[1];
    const float* Wout = (const float*)d_in[2];
    const float* gamma = (const float*)d_in[3];
    float* out = (float*)d_out;

    k_prep<<<256, 256>>>(Wqkv, Wout);
    k_qkv<<<dim3(32, NB), 256, 18432 + 27648>>>(v);
    k_lsum<<<dim3(32, NB), 256, 36864>>>();
    k_attn<<<dim3(32, NB), 256, 36864>>>();
    k_out<<<dim3(32, 4, NB), 128, 33792>>>(v, gamma, out);
}